// round 1
// baseline (speedup 1.0000x reference)
#include <cuda_runtime.h>
#include <cuda_bf16.h>
#include <mma.h>

using namespace nvcuda;

#define B_  4
#define H_  16
#define SQ  2048
#define DH  64
#define BM  32
#define BN  64
#define NITER (SQ / BN)      // 32
#define THREADS 256

// smem layout (bytes):
//  Ssm   : 32 x 68 fp32          = 8704
//  Qh,Ql : 32 x 72 bf16          = 4608 each
//  Kh,Kl : 64 x 72 bf16          = 9216 each
//  Vh,Vl : 64 x 72 bf16          = 9216 each
//  Eh,El : 32 x 72 bf16          = 4608 each
//  rowsum: 32 fp32, rinv: 32 fp32
#define SMEM_BYTES (8704 + 2*4608 + 4*9216 + 2*4608 + 256)

__device__ __forceinline__ void split_bf16(float x, __nv_bfloat16& h, __nv_bfloat16& l) {
    h = __float2bfloat16(x);
    l = __float2bfloat16(x - __bfloat162float(h));
}

__global__ void __launch_bounds__(THREADS)
attn_kernel(const float* __restrict__ q, const float* __restrict__ k,
            const float* __restrict__ v, const int* __restrict__ mask,
            float* __restrict__ outp, float* __restrict__ pattn)
{
    extern __shared__ char smem[];
    float*         Ssm = (float*)smem;                       // 32 x 68
    __nv_bfloat16* Qh  = (__nv_bfloat16*)(smem + 8704);
    __nv_bfloat16* Ql  = Qh + 32 * 72;
    __nv_bfloat16* Kh  = Ql + 32 * 72;
    __nv_bfloat16* Kl  = Kh + 64 * 72;
    __nv_bfloat16* Vh  = Kl + 64 * 72;
    __nv_bfloat16* Vl  = Vh + 64 * 72;
    __nv_bfloat16* Eh  = Vl + 64 * 72;
    __nv_bfloat16* El  = Eh + 32 * 72;
    float*      rowsum = (float*)(El + 32 * 72);
    float*      rinv   = rowsum + 32;

    const int tid  = threadIdx.x;
    const int warp = tid >> 5;
    const int lane = tid & 31;
    const int wm   = warp >> 2;          // 0..1  (16-row band)
    const int wn   = warp & 3;           // 0..3  (16-col band)
    const int m0   = blockIdx.x * BM;
    const int bh   = blockIdx.y;

    const float* qb = q + (size_t)bh * SQ * DH;
    const float* kb = k + (size_t)bh * SQ * DH;
    const float* vb = v + (size_t)bh * SQ * DH;
    float*       pb = pattn + (size_t)bh * SQ * SQ;

    // ---- load & split Q tile [32 x 64] ----
    #pragma unroll
    for (int i = 0; i < 2; i++) {
        int s  = tid + i * THREADS;          // 512 float4 slots
        int r  = s >> 4;
        int c4 = (s & 15) * 4;
        float4 x = *(const float4*)(qb + (size_t)(m0 + r) * DH + c4);
        const float* xv = (const float*)&x;
        #pragma unroll
        for (int j = 0; j < 4; j++) {
            __nv_bfloat16 h, l;
            split_bf16(xv[j], h, l);
            Qh[r * 72 + c4 + j] = h;
            Ql[r * 72 + c4 + j] = l;
        }
    }

    float rs0 = 0.f, rs1 = 0.f;          // per-thread rowsum partials (2 fixed rows)

    wmma::fragment<wmma::accumulator, 16, 16, 16, float> o_acc;
    wmma::fill_fragment(o_acc, 0.f);

    for (int it = 0; it < NITER; it++) {
        const int n0 = it * BN;
        __syncthreads();   // protects Kh/Vh/Eh from prior-iteration readers

        // ---- load & split K,V tiles [64 x 64] ----
        #pragma unroll
        for (int i = 0; i < 4; i++) {
            int s  = tid + i * THREADS;      // 1024 float4 slots
            int r  = s >> 4;
            int c4 = (s & 15) * 4;
            float4 kx = *(const float4*)(kb + (size_t)(n0 + r) * DH + c4);
            float4 vx = *(const float4*)(vb + (size_t)(n0 + r) * DH + c4);
            const float* kv = (const float*)&kx;
            const float* vv = (const float*)&vx;
            #pragma unroll
            for (int j = 0; j < 4; j++) {
                __nv_bfloat16 h, l;
                split_bf16(kv[j], h, l);
                Kh[r * 72 + c4 + j] = h;
                Kl[r * 72 + c4 + j] = l;
                split_bf16(vv[j], h, l);
                Vh[r * 72 + c4 + j] = h;
                Vl[r * 72 + c4 + j] = l;
            }
        }
        __syncthreads();

        // ---- QK^T : S[32x64], each warp one 16x16 tile, 3-mma bf16 split ----
        {
            wmma::fragment<wmma::accumulator, 16, 16, 16, float> sacc;
            wmma::fill_fragment(sacc, 0.f);
            #pragma unroll
            for (int kk = 0; kk < 4; kk++) {
                wmma::fragment<wmma::matrix_a, 16, 16, 16, __nv_bfloat16, wmma::row_major> ah, al;
                wmma::fragment<wmma::matrix_b, 16, 16, 16, __nv_bfloat16, wmma::col_major> bh, bl;
                wmma::load_matrix_sync(ah, Qh + wm * 16 * 72 + kk * 16, 72);
                wmma::load_matrix_sync(al, Ql + wm * 16 * 72 + kk * 16, 72);
                wmma::load_matrix_sync(bh, Kh + wn * 16 * 72 + kk * 16, 72);
                wmma::load_matrix_sync(bl, Kl + wn * 16 * 72 + kk * 16, 72);
                wmma::mma_sync(sacc, ah, bh, sacc);
                wmma::mma_sync(sacc, ah, bl, sacc);
                wmma::mma_sync(sacc, al, bh, sacc);
            }
            wmma::store_matrix_sync(Ssm + wm * 16 * 68 + wn * 16, sacc, 68, wmma::mem_row_major);
        }
        __syncthreads();

        // ---- elementwise: e = mask ? exp(s/8) : 0 ; store p (unnorm), Eh/El, rowsum ----
        #pragma unroll
        for (int i = 0; i < 2; i++) {
            int s  = tid + i * THREADS;
            int r  = s >> 4;
            int c4 = (s & 15) * 4;
            float4 sv = *(const float4*)(Ssm + r * 68 + c4);
            int4   mv = *(const int4*)(mask + (size_t)(m0 + r) * SQ + n0 + c4);
            float e0 = mv.x ? __expf(0.125f * sv.x) : 0.f;
            float e1 = mv.y ? __expf(0.125f * sv.y) : 0.f;
            float e2 = mv.z ? __expf(0.125f * sv.z) : 0.f;
            float e3 = mv.w ? __expf(0.125f * sv.w) : 0.f;
            float4 ev = make_float4(e0, e1, e2, e3);
            *(float4*)(pb + (size_t)(m0 + r) * SQ + n0 + c4) = ev;
            float partial = (e0 + e1) + (e2 + e3);
            if (i == 0) rs0 += partial; else rs1 += partial;
            const float* ep = (const float*)&ev;
            #pragma unroll
            for (int j = 0; j < 4; j++) {
                __nv_bfloat16 h, l;
                split_bf16(ep[j], h, l);
                Eh[r * 72 + c4 + j] = h;
                El[r * 72 + c4 + j] = l;
            }
        }
        __syncthreads();

        // ---- O += E @ V : each warp one 16x16 tile of O[32x64] ----
        #pragma unroll
        for (int kk = 0; kk < 4; kk++) {
            wmma::fragment<wmma::matrix_a, 16, 16, 16, __nv_bfloat16, wmma::row_major> ah, al;
            wmma::fragment<wmma::matrix_b, 16, 16, 16, __nv_bfloat16, wmma::row_major> bh, bl;
            wmma::load_matrix_sync(ah, Eh + wm * 16 * 72 + kk * 16, 72);
            wmma::load_matrix_sync(al, El + wm * 16 * 72 + kk * 16, 72);
            wmma::load_matrix_sync(bh, Vh + kk * 16 * 72 + wn * 16, 72);
            wmma::load_matrix_sync(bl, Vl + kk * 16 * 72 + wn * 16, 72);
            wmma::mma_sync(o_acc, ah, bh, o_acc);
            wmma::mma_sync(o_acc, ah, bl, o_acc);
            wmma::mma_sync(o_acc, al, bh, o_acc);
        }
    }

    __syncthreads();

    // ---- rowsum reduction: thread t owns rows t/16 (rs0) and 16+t/16 (rs1) ----
    #pragma unroll
    for (int off = 8; off >= 1; off >>= 1) {
        rs0 += __shfl_down_sync(0xffffffffu, rs0, off, 16);
        rs1 += __shfl_down_sync(0xffffffffu, rs1, off, 16);
    }
    if (lane == 0)  { rowsum[2 * warp]          = rs0; rowsum[16 + 2 * warp]     = rs1; }
    if (lane == 16) { rowsum[2 * warp + 1]      = rs0; rowsum[17 + 2 * warp]     = rs1; }
    __syncthreads();
    if (tid < 32) {
        float rsv = rowsum[tid];
        rinv[tid] = (rsv > 0.f) ? (1.f / rsv) : 0.f;
    }

    // ---- write O (normalized) ----
    wmma::store_matrix_sync(Ssm + wm * 16 * 68 + wn * 16, o_acc, 68, wmma::mem_row_major);
    __syncthreads();
    #pragma unroll
    for (int i = 0; i < 2; i++) {
        int s  = tid + i * THREADS;
        int r  = s >> 4;
        int c4 = (s & 15) * 4;
        float sc = rinv[r];
        float4 ov = *(const float4*)(Ssm + r * 68 + c4);
        ov.x *= sc; ov.y *= sc; ov.z *= sc; ov.w *= sc;
        *(float4*)(outp + (size_t)((size_t)bh * SQ + m0 + r) * DH + c4) = ov;
    }

    // ---- phase 2: normalize this CTA's p tile (read-back, mostly L2-resident) ----
    for (int it = 0; it < NITER; it++) {
        #pragma unroll
        for (int i = 0; i < 2; i++) {
            int s  = tid + i * THREADS;
            int r  = s >> 4;
            int c4 = (s & 15) * 4;
            float sc = rinv[r];
            float4* pp = (float4*)(pb + (size_t)(m0 + r) * SQ + it * BN + c4);
            float4 pv = *pp;
            pv.x *= sc; pv.y *= sc; pv.z *= sc; pv.w *= sc;
            *pp = pv;
        }
    }
}

extern "C" void kernel_launch(void* const* d_in, const int* in_sizes, int n_in,
                              void* d_out, int out_size)
{
    const float* q    = (const float*)d_in[0];
    const float* k    = (const float*)d_in[1];
    const float* v    = (const float*)d_in[2];
    const int*   mask = (const int*)d_in[3];

    float* outp  = (float*)d_out;                                   // [B,H,S,D]
    float* pattn = (float*)d_out + (size_t)B_ * H_ * SQ * DH;       // [B,H,S,S]

    cudaFuncSetAttribute(attn_kernel, cudaFuncAttributeMaxDynamicSharedMemorySize, SMEM_BYTES);

    dim3 grid(SQ / BM, B_ * H_);   // x: query blocks (same-head CTAs adjacent), y: head
    attn_kernel<<<grid, THREADS, SMEM_BYTES>>>(q, k, v, mask, outp, pattn);
}

// round 4
// speedup vs baseline: 1.4371x; 1.4371x over previous
#include <cuda_runtime.h>
#include <cuda_fp16.h>
#include <cstdint>

#define B_  4
#define H_  16
#define SQ  2048
#define DH  64
#define BM  128
#define BN  64
#define NITER (SQ / BN)     // 32
#define THREADS 256
#define STRD 72             // smem row stride in halves (bank-conflict-free for ldmatrix)

// smem (halves): Qh[128*72] Ql[128*72] Kh[64*72] Kl[64*72] Vh[64*72], then rinv float[128]
#define SMEM_BYTES ((128*STRD*2 + 64*STRD*3) * 2 + 512)

__device__ __forceinline__ uint32_t smaddr(const void* p) {
    return (uint32_t)__cvta_generic_to_shared(p);
}

__device__ __forceinline__ void ldmx4(uint32_t r[4], uint32_t addr) {
    asm volatile("ldmatrix.sync.aligned.m8n8.x4.shared.b16 {%0,%1,%2,%3},[%4];"
                 : "=r"(r[0]), "=r"(r[1]), "=r"(r[2]), "=r"(r[3]) : "r"(addr));
}
__device__ __forceinline__ void ldmx4t(uint32_t r[4], uint32_t addr) {
    asm volatile("ldmatrix.sync.aligned.m8n8.x4.trans.shared.b16 {%0,%1,%2,%3},[%4];"
                 : "=r"(r[0]), "=r"(r[1]), "=r"(r[2]), "=r"(r[3]) : "r"(addr));
}
__device__ __forceinline__ void mma16816(float c[4], uint32_t a0, uint32_t a1, uint32_t a2,
                                         uint32_t a3, uint32_t b0, uint32_t b1) {
    asm volatile("mma.sync.aligned.m16n8k16.row.col.f32.f16.f16.f32 "
                 "{%0,%1,%2,%3},{%4,%5,%6,%7},{%8,%9},{%0,%1,%2,%3};"
                 : "+f"(c[0]), "+f"(c[1]), "+f"(c[2]), "+f"(c[3])
                 : "r"(a0), "r"(a1), "r"(a2), "r"(a3), "r"(b0), "r"(b1));
}
__device__ __forceinline__ uint32_t packh2(float a, float b) {
    __half2 h = __floats2half2_rn(a, b);
    return *(uint32_t*)&h;
}

__global__ void __launch_bounds__(THREADS, 2)
attn_kernel(const float* __restrict__ q, const float* __restrict__ k,
            const float* __restrict__ v, const int* __restrict__ mask,
            float* __restrict__ outp, float* __restrict__ pattn)
{
    extern __shared__ __half sm[];
    __half* Qh = sm;
    __half* Ql = Qh + 128 * STRD;
    __half* Kh = Ql + 128 * STRD;
    __half* Kl = Kh + 64 * STRD;
    __half* Vh = Kl + 64 * STRD;
    float*  rinv_s = (float*)(Vh + 64 * STRD);

    const int tid  = threadIdx.x;
    const int lane = tid & 31;
    const int warp = tid >> 5;
    const int g    = lane >> 2;        // row group 0..7
    const int tq   = lane & 3;         // quad id
    const int wrow = warp * 16;
    const int m0   = blockIdx.x * BM;
    const int bh   = blockIdx.y;

    const float* qb = q + (size_t)bh * SQ * DH;
    const float* kb = k + (size_t)bh * SQ * DH;
    const float* vb = v + (size_t)bh * SQ * DH;
    float*       pb = pattn + (size_t)bh * SQ * SQ;

    // ---- prologue: load+split Q [128x64] fp32 -> fp16 hi/lo (packed 8B STS) ----
    #pragma unroll
    for (int i = 0; i < 8; i++) {
        int s  = tid + i * THREADS;        // 2048 float4 slots
        int r  = s >> 4;
        int c4 = (s & 15) * 4;
        float4 x = *(const float4*)(qb + (size_t)(m0 + r) * DH + c4);
        const float* xv = (const float*)&x;
        __half h[4]; float lo[4];
        #pragma unroll
        for (int j = 0; j < 4; j++) { h[j] = __float2half_rn(xv[j]); lo[j] = xv[j] - __half2float(h[j]); }
        uint2 uh, ul;
        uh.x = packh2(__half2float(h[0]), __half2float(h[1]));
        uh.y = packh2(__half2float(h[2]), __half2float(h[3]));
        ul.x = packh2(lo[0], lo[1]);
        ul.y = packh2(lo[2], lo[3]);
        *(uint2*)&Qh[r * STRD + c4] = uh;
        *(uint2*)&Ql[r * STRD + c4] = ul;
    }

    float oacc[8][4];
    #pragma unroll
    for (int j = 0; j < 8; j++) { oacc[j][0]=0.f; oacc[j][1]=0.f; oacc[j][2]=0.f; oacc[j][3]=0.f; }
    float rs0 = 0.f, rs1 = 0.f;
    const int prow0 = m0 + wrow + g;       // global row for c0/c1 lanes

    for (int it = 0; it < NITER; it++) {
        const int n0 = it * BN;
        __syncthreads();    // protect K/V smem from previous iteration readers (covers Q on it 0)

        // ---- load+split K [64x64] hi/lo, V hi only ----
        #pragma unroll
        for (int i = 0; i < 4; i++) {
            int s  = tid + i * THREADS;    // 1024 slots
            int r  = s >> 4;
            int c4 = (s & 15) * 4;
            float4 kx = *(const float4*)(kb + (size_t)(n0 + r) * DH + c4);
            float4 vx = *(const float4*)(vb + (size_t)(n0 + r) * DH + c4);
            const float* kv = (const float*)&kx;
            const float* vv = (const float*)&vx;
            __half kh[4]; float klo[4];
            #pragma unroll
            for (int j = 0; j < 4; j++) { kh[j] = __float2half_rn(kv[j]); klo[j] = kv[j] - __half2float(kh[j]); }
            uint2 ukh, ukl, uvh;
            ukh.x = packh2(__half2float(kh[0]), __half2float(kh[1]));
            ukh.y = packh2(__half2float(kh[2]), __half2float(kh[3]));
            ukl.x = packh2(klo[0], klo[1]);
            ukl.y = packh2(klo[2], klo[3]);
            uvh.x = packh2(vv[0], vv[1]);
            uvh.y = packh2(vv[2], vv[3]);
            *(uint2*)&Kh[r * STRD + c4] = ukh;
            *(uint2*)&Kl[r * STRD + c4] = ukl;
            *(uint2*)&Vh[r * STRD + c4] = uvh;
        }
        __syncthreads();

        // ---- QK^T: S[16x64] per warp in regs, fp16 hi/lo 3-mma split ----
        float sacc[8][4];
        #pragma unroll
        for (int j = 0; j < 8; j++) { sacc[j][0]=0.f; sacc[j][1]=0.f; sacc[j][2]=0.f; sacc[j][3]=0.f; }

        #pragma unroll
        for (int kc = 0; kc < 4; kc++) {
            uint32_t aq[4], al[4];
            {
                int row = wrow + (lane & 15);
                int col = kc * 16 + ((lane & 16) ? 8 : 0);
                ldmx4(aq, smaddr(&Qh[row * STRD + col]));
                ldmx4(al, smaddr(&Ql[row * STRD + col]));
            }
            #pragma unroll
            for (int jp = 0; jp < 4; jp++) {
                uint32_t bh4[4], bl4[4];
                int row = jp * 16 + (lane & 7) + ((lane & 16) ? 8 : 0);
                int col = kc * 16 + ((lane & 8) ? 8 : 0);
                ldmx4(bh4, smaddr(&Kh[row * STRD + col]));
                ldmx4(bl4, smaddr(&Kl[row * STRD + col]));
                mma16816(sacc[2*jp],   aq[0],aq[1],aq[2],aq[3], bh4[0], bh4[1]);
                mma16816(sacc[2*jp],   aq[0],aq[1],aq[2],aq[3], bl4[0], bl4[1]);
                mma16816(sacc[2*jp],   al[0],al[1],al[2],al[3], bh4[0], bh4[1]);
                mma16816(sacc[2*jp+1], aq[0],aq[1],aq[2],aq[3], bh4[2], bh4[3]);
                mma16816(sacc[2*jp+1], aq[0],aq[1],aq[2],aq[3], bl4[2], bl4[3]);
                mma16816(sacc[2*jp+1], al[0],al[1],al[2],al[3], bh4[2], bh4[3]);
            }
        }

        // ---- elementwise in regs: mask, exp, rowsum, store p, pack P for PV ----
        uint32_t pk[8][2];
        #pragma unroll
        for (int j = 0; j < 8; j++) {
            int col = n0 + j * 8 + 2 * tq;
            int2 mz0 = *(const int2*)(mask + (size_t)prow0 * SQ + col);
            int2 mz1 = *(const int2*)(mask + (size_t)(prow0 + 8) * SQ + col);
            float e0 = mz0.x ? __expf(0.125f * sacc[j][0]) : 0.f;
            float e1 = mz0.y ? __expf(0.125f * sacc[j][1]) : 0.f;
            float e2 = mz1.x ? __expf(0.125f * sacc[j][2]) : 0.f;
            float e3 = mz1.y ? __expf(0.125f * sacc[j][3]) : 0.f;
            float2 p0; p0.x = e0; p0.y = e1;
            float2 p1; p1.x = e2; p1.y = e3;
            *(float2*)(pb + (size_t)prow0 * SQ + col)       = p0;
            *(float2*)(pb + (size_t)(prow0 + 8) * SQ + col) = p1;
            rs0 += e0 + e1;
            rs1 += e2 + e3;
            pk[j][0] = packh2(e0, e1);
            pk[j][1] = packh2(e2, e3);
        }

        // ---- O += P @ V  (P direct from accumulator regs, single fp16 mma) ----
        #pragma unroll
        for (int kcp = 0; kcp < 4; kcp++) {
            uint32_t a0 = pk[2*kcp][0], a1 = pk[2*kcp][1];
            uint32_t a2 = pk[2*kcp+1][0], a3 = pk[2*kcp+1][1];
            #pragma unroll
            for (int jdp = 0; jdp < 4; jdp++) {
                uint32_t bv[4];
                int row = kcp * 16 + (lane & 7) + ((lane & 8) ? 8 : 0);
                int col = jdp * 16 + ((lane & 16) ? 8 : 0);
                ldmx4t(bv, smaddr(&Vh[row * STRD + col]));
                mma16816(oacc[2*jdp],   a0,a1,a2,a3, bv[0], bv[1]);
                mma16816(oacc[2*jdp+1], a0,a1,a2,a3, bv[2], bv[3]);
            }
        }
    }

    // ---- rowsum reduce within quad, O store, rinv to smem ----
    rs0 += __shfl_xor_sync(0xffffffffu, rs0, 1);
    rs0 += __shfl_xor_sync(0xffffffffu, rs0, 2);
    rs1 += __shfl_xor_sync(0xffffffffu, rs1, 1);
    rs1 += __shfl_xor_sync(0xffffffffu, rs1, 2);
    float ri0 = (rs0 > 0.f) ? (1.f / rs0) : 0.f;
    float ri1 = (rs1 > 0.f) ? (1.f / rs1) : 0.f;

    #pragma unroll
    for (int jd = 0; jd < 8; jd++) {
        int col = jd * 8 + 2 * tq;
        float2 o0; o0.x = oacc[jd][0] * ri0; o0.y = oacc[jd][1] * ri0;
        float2 o1; o1.x = oacc[jd][2] * ri1; o1.y = oacc[jd][3] * ri1;
        *(float2*)(outp + ((size_t)bh * SQ + prow0) * DH + col)     = o0;
        *(float2*)(outp + ((size_t)bh * SQ + prow0 + 8) * DH + col) = o1;
    }
    if (tq == 0) {
        rinv_s[wrow + g]     = ri0;
        rinv_s[wrow + g + 8] = ri1;
    }
    __syncthreads();

    // ---- phase 2: normalize this CTA's p band [128 x 2048] ----
    #pragma unroll 4
    for (int i = 0; i < 256; i++) {
        int s  = tid + i * THREADS;          // 65536 float4 slots
        int r  = s >> 9;
        int c4 = (s & 511) * 4;
        float sc = rinv_s[r];
        float4* pp = (float4*)(pb + (size_t)(m0 + r) * SQ + c4);
        float4 pv = *pp;
        pv.x *= sc; pv.y *= sc; pv.z *= sc; pv.w *= sc;
        *pp = pv;
    }
}

extern "C" void kernel_launch(void* const* d_in, const int* in_sizes, int n_in,
                              void* d_out, int out_size)
{
    const float* q    = (const float*)d_in[0];
    const float* k    = (const float*)d_in[1];
    const float* v    = (const float*)d_in[2];
    const int*   mask = (const int*)d_in[3];

    float* outp  = (float*)d_out;                                   // [B,H,S,D]
    float* pattn = (float*)d_out + (size_t)B_ * H_ * SQ * DH;       // [B,H,S,S]

    cudaFuncSetAttribute(attn_kernel, cudaFuncAttributeMaxDynamicSharedMemorySize, SMEM_BYTES);

    dim3 grid(SQ / BM, B_ * H_);
    attn_kernel<<<grid, THREADS, SMEM_BYTES>>>(q, k, v, mask, outp, pattn);
}

// round 6
// speedup vs baseline: 1.9607x; 1.3644x over previous
#include <cuda_runtime.h>
#include <cuda_fp16.h>
#include <cstdint>

#define B_  4
#define H_  16
#define SQ  2048
#define DH  64
#define BM  128
#define BN  64
#define NITER (SQ / BN)     // 32
#define THREADS 256
#define STRD 72             // fp16 smem row stride (halves)

// 512 MB device scratch: unnormalized exp(s) in fp16, layout [B*H*S, S]
__device__ __half e_scratch[(size_t)B_ * H_ * SQ * SQ];

// smem layout (bytes):
//   0      Qh  128x72 half   18432
//   18432  Ql  128x72 half   18432
//   36864  Kh   64x72 half    9216
//   46080  Kl   64x72 half    9216
//   55296  Vh   64x72 half    9216
//   64512  Kst  64x64 fp32   16384   (cp.async staging)
//   80896  Vst  64x64 fp32   16384
#define SMEM_BYTES 97280

__device__ __forceinline__ uint32_t smaddr(const void* p) {
    return (uint32_t)__cvta_generic_to_shared(p);
}
__device__ __forceinline__ void cpa16(uint32_t s, const void* g) {
    asm volatile("cp.async.cg.shared.global [%0],[%1],16;" :: "r"(s), "l"(g));
}
__device__ __forceinline__ void cpa_commit() {
    asm volatile("cp.async.commit_group;");
}
template<int N> __device__ __forceinline__ void cpa_wait() {
    asm volatile("cp.async.wait_group %0;" :: "n"(N));
}
__device__ __forceinline__ void ldmx4(uint32_t r[4], uint32_t addr) {
    asm volatile("ldmatrix.sync.aligned.m8n8.x4.shared.b16 {%0,%1,%2,%3},[%4];"
                 : "=r"(r[0]), "=r"(r[1]), "=r"(r[2]), "=r"(r[3]) : "r"(addr));
}
__device__ __forceinline__ void ldmx4t(uint32_t r[4], uint32_t addr) {
    asm volatile("ldmatrix.sync.aligned.m8n8.x4.trans.shared.b16 {%0,%1,%2,%3},[%4];"
                 : "=r"(r[0]), "=r"(r[1]), "=r"(r[2]), "=r"(r[3]) : "r"(addr));
}
__device__ __forceinline__ void mma16816(float c[4], uint32_t a0, uint32_t a1, uint32_t a2,
                                         uint32_t a3, uint32_t b0, uint32_t b1) {
    asm volatile("mma.sync.aligned.m16n8k16.row.col.f32.f16.f16.f32 "
                 "{%0,%1,%2,%3},{%4,%5,%6,%7},{%8,%9},{%0,%1,%2,%3};"
                 : "+f"(c[0]), "+f"(c[1]), "+f"(c[2]), "+f"(c[3])
                 : "r"(a0), "r"(a1), "r"(a2), "r"(a3), "r"(b0), "r"(b1));
}
__device__ __forceinline__ uint32_t packh2(float a, float b) {
    __half2 h = __floats2half2_rn(a, b);
    return *(uint32_t*)&h;
}

// ==================== k1: QK, exp, e-store (fp16), PV, O ====================
__global__ void __launch_bounds__(THREADS, 2)
attn_k1(const float* __restrict__ q, const float* __restrict__ k,
        const float* __restrict__ v, const int* __restrict__ mask,
        float* __restrict__ outp)
{
    extern __shared__ char smem[];
    __half* Qh = (__half*)smem;
    __half* Ql = Qh + 128 * STRD;
    __half* Kh = Ql + 128 * STRD;
    __half* Kl = Kh + 64 * STRD;
    __half* Vh = Kl + 64 * STRD;
    float*  Kst = (float*)(smem + 64512);
    float*  Vst = Kst + 64 * 64;

    const int tid  = threadIdx.x;
    const int lane = tid & 31;
    const int warp = tid >> 5;
    const int g    = lane >> 2;
    const int tq   = lane & 3;
    const int wrow = warp * 16;
    const int m0   = blockIdx.x * BM;
    const int bh   = blockIdx.y;

    const float* qb = q + (size_t)bh * SQ * DH;
    const float* kb = k + (size_t)bh * SQ * DH;
    const float* vb = v + (size_t)bh * SQ * DH;
    __half*      eb = e_scratch + (size_t)bh * SQ * SQ;

    // ---- prologue: prefetch K0,V0 via cp.async; load+split Q ----
    #pragma unroll
    for (int i = 0; i < 4; i++) {
        int s = tid + i * THREADS;
        cpa16(smaddr(Kst + s * 4), kb + s * 4);
    }
    cpa_commit();
    #pragma unroll
    for (int i = 0; i < 4; i++) {
        int s = tid + i * THREADS;
        cpa16(smaddr(Vst + s * 4), vb + s * 4);
    }
    cpa_commit();

    #pragma unroll
    for (int i = 0; i < 8; i++) {
        int s  = tid + i * THREADS;
        int r  = s >> 4;
        int c4 = (s & 15) * 4;
        float4 x = *(const float4*)(qb + (size_t)(m0 + r) * DH + c4);
        const float* xv = (const float*)&x;
        __half h[4]; float lo[4];
        #pragma unroll
        for (int j = 0; j < 4; j++) { h[j] = __float2half_rn(xv[j]); lo[j] = xv[j] - __half2float(h[j]); }
        uint2 uh, ul;
        uh.x = packh2(__half2float(h[0]), __half2float(h[1]));
        uh.y = packh2(__half2float(h[2]), __half2float(h[3]));
        ul.x = packh2(lo[0], lo[1]);
        ul.y = packh2(lo[2], lo[3]);
        *(uint2*)&Qh[r * STRD + c4] = uh;
        *(uint2*)&Ql[r * STRD + c4] = ul;
    }

    cpa_wait<1>();   // K0 landed
    // convert K0 -> Kh/Kl
    #pragma unroll
    for (int i = 0; i < 4; i++) {
        int s  = tid + i * THREADS;
        int r  = s >> 4;
        int c4 = (s & 15) * 4;
        float4 kx = *(const float4*)(Kst + s * 4);
        const float* kv = (const float*)&kx;
        __half kh[4]; float klo[4];
        #pragma unroll
        for (int j = 0; j < 4; j++) { kh[j] = __float2half_rn(kv[j]); klo[j] = kv[j] - __half2float(kh[j]); }
        uint2 ukh, ukl;
        ukh.x = packh2(__half2float(kh[0]), __half2float(kh[1]));
        ukh.y = packh2(__half2float(kh[2]), __half2float(kh[3]));
        ukl.x = packh2(klo[0], klo[1]);
        ukl.y = packh2(klo[2], klo[3]);
        *(uint2*)&Kh[r * STRD + c4] = ukh;
        *(uint2*)&Kl[r * STRD + c4] = ukl;
    }

    float oacc[8][4];
    #pragma unroll
    for (int j = 0; j < 8; j++) { oacc[j][0]=0.f; oacc[j][1]=0.f; oacc[j][2]=0.f; oacc[j][3]=0.f; }
    float rs0 = 0.f, rs1 = 0.f;
    const int prow0 = m0 + wrow + g;

    for (int it = 0; it < NITER; it++) {
        const int n0 = it * BN;
        const int nn = ((it + 1 < NITER) ? (it + 1) : 0) * BN;
        __syncthreads();   // alpha: Kh/Kl(it) ready; Kst free; Vh free

        // prefetch K(it+1) into staging
        #pragma unroll
        for (int i = 0; i < 4; i++) {
            int s = tid + i * THREADS;
            cpa16(smaddr(Kst + s * 4), kb + (size_t)nn * DH + s * 4);
        }
        cpa_commit();

        // ---- QK^T: S[16x64] per warp, fp16 hi/lo 3-mma split ----
        float sacc[8][4];
        #pragma unroll
        for (int j = 0; j < 8; j++) { sacc[j][0]=0.f; sacc[j][1]=0.f; sacc[j][2]=0.f; sacc[j][3]=0.f; }

        #pragma unroll
        for (int kc = 0; kc < 4; kc++) {
            uint32_t aq[4], al[4];
            {
                int row = wrow + (lane & 15);
                int col = kc * 16 + ((lane & 16) ? 8 : 0);
                ldmx4(aq, smaddr(&Qh[row * STRD + col]));
                ldmx4(al, smaddr(&Ql[row * STRD + col]));
            }
            #pragma unroll
            for (int jp = 0; jp < 4; jp++) {
                uint32_t bh4[4], bl4[4];
                int row = jp * 16 + (lane & 7) + ((lane & 16) ? 8 : 0);
                int col = kc * 16 + ((lane & 8) ? 8 : 0);
                ldmx4(bh4, smaddr(&Kh[row * STRD + col]));
                ldmx4(bl4, smaddr(&Kl[row * STRD + col]));
                mma16816(sacc[2*jp],   aq[0],aq[1],aq[2],aq[3], bh4[0], bh4[1]);
                mma16816(sacc[2*jp],   aq[0],aq[1],aq[2],aq[3], bl4[0], bl4[1]);
                mma16816(sacc[2*jp],   al[0],al[1],al[2],al[3], bh4[0], bh4[1]);
                mma16816(sacc[2*jp+1], aq[0],aq[1],aq[2],aq[3], bh4[2], bh4[3]);
                mma16816(sacc[2*jp+1], aq[0],aq[1],aq[2],aq[3], bl4[2], bl4[3]);
                mma16816(sacc[2*jp+1], al[0],al[1],al[2],al[3], bh4[2], bh4[3]);
            }
        }

        // ---- mask, exp, rowsum, e-store (fp16 scratch), pack P ----
        uint32_t pk[8][2];
        #pragma unroll
        for (int j = 0; j < 8; j++) {
            int col = n0 + j * 8 + 2 * tq;
            int2 mz0 = *(const int2*)(mask + (size_t)prow0 * SQ + col);
            int2 mz1 = *(const int2*)(mask + (size_t)(prow0 + 8) * SQ + col);
            float e0 = mz0.x ? __expf(0.125f * sacc[j][0]) : 0.f;
            float e1 = mz0.y ? __expf(0.125f * sacc[j][1]) : 0.f;
            float e2 = mz1.x ? __expf(0.125f * sacc[j][2]) : 0.f;
            float e3 = mz1.y ? __expf(0.125f * sacc[j][3]) : 0.f;
            rs0 += e0 + e1;
            rs1 += e2 + e3;
            uint32_t p01 = packh2(e0, e1);
            uint32_t p23 = packh2(e2, e3);
            *(uint32_t*)(eb + (size_t)prow0 * SQ + col)       = p01;
            *(uint32_t*)(eb + (size_t)(prow0 + 8) * SQ + col) = p23;
            pk[j][0] = p01;
            pk[j][1] = p23;
        }

        // V(it) has landed (oldest pending group); convert to Vh
        cpa_wait<1>();
        #pragma unroll
        for (int i = 0; i < 4; i++) {
            int s  = tid + i * THREADS;
            int r  = s >> 4;
            int c4 = (s & 15) * 4;
            float4 vx = *(const float4*)(Vst + s * 4);
            uint2 uvh;
            uvh.x = packh2(vx.x, vx.y);
            uvh.y = packh2(vx.z, vx.w);
            *(uint2*)&Vh[r * STRD + c4] = uvh;
        }
        __syncthreads();   // beta: Vh ready for all warps; Vst free

        // prefetch V(it+1)
        #pragma unroll
        for (int i = 0; i < 4; i++) {
            int s = tid + i * THREADS;
            cpa16(smaddr(Vst + s * 4), vb + (size_t)nn * DH + s * 4);
        }
        cpa_commit();

        // ---- O += P @ V ----
        #pragma unroll
        for (int kcp = 0; kcp < 4; kcp++) {
            uint32_t a0 = pk[2*kcp][0], a1 = pk[2*kcp][1];
            uint32_t a2 = pk[2*kcp+1][0], a3 = pk[2*kcp+1][1];
            #pragma unroll
            for (int jdp = 0; jdp < 4; jdp++) {
                uint32_t bv[4];
                int row = kcp * 16 + (lane & 7) + ((lane & 8) ? 8 : 0);
                int col = jdp * 16 + ((lane & 16) ? 8 : 0);
                ldmx4t(bv, smaddr(&Vh[row * STRD + col]));
                mma16816(oacc[2*jdp],   a0,a1,a2,a3, bv[0], bv[1]);
                mma16816(oacc[2*jdp+1], a0,a1,a2,a3, bv[2], bv[3]);
            }
        }

        // K(it+1) landed; convert to Kh/Kl for next iteration
        cpa_wait<1>();
        #pragma unroll
        for (int i = 0; i < 4; i++) {
            int s  = tid + i * THREADS;
            int r  = s >> 4;
            int c4 = (s & 15) * 4;
            float4 kx = *(const float4*)(Kst + s * 4);
            const float* kv = (const float*)&kx;
            __half kh[4]; float klo[4];
            #pragma unroll
            for (int j = 0; j < 4; j++) { kh[j] = __float2half_rn(kv[j]); klo[j] = kv[j] - __half2float(kh[j]); }
            uint2 ukh, ukl;
            ukh.x = packh2(__half2float(kh[0]), __half2float(kh[1]));
            ukh.y = packh2(__half2float(kh[2]), __half2float(kh[3]));
            ukl.x = packh2(klo[0], klo[1]);
            ukl.y = packh2(klo[2], klo[3]);
            *(uint2*)&Kh[r * STRD + c4] = ukh;
            *(uint2*)&Kl[r * STRD + c4] = ukl;
        }
    }
    cpa_wait<0>();

    // ---- rowsum reduce within quad; write normalized O ----
    rs0 += __shfl_xor_sync(0xffffffffu, rs0, 1);
    rs0 += __shfl_xor_sync(0xffffffffu, rs0, 2);
    rs1 += __shfl_xor_sync(0xffffffffu, rs1, 1);
    rs1 += __shfl_xor_sync(0xffffffffu, rs1, 2);
    float ri0 = (rs0 > 0.f) ? (1.f / rs0) : 0.f;
    float ri1 = (rs1 > 0.f) ? (1.f / rs1) : 0.f;

    #pragma unroll
    for (int jd = 0; jd < 8; jd++) {
        int col = jd * 8 + 2 * tq;
        float2 o0; o0.x = oacc[jd][0] * ri0; o0.y = oacc[jd][1] * ri0;
        float2 o1; o1.x = oacc[jd][2] * ri1; o1.y = oacc[jd][3] * ri1;
        *(float2*)(outp + ((size_t)bh * SQ + prow0) * DH + col)     = o0;
        *(float2*)(outp + ((size_t)bh * SQ + prow0 + 8) * DH + col) = o1;
    }
}

// ==================== k2: stream-normalize p (1 warp / row) ====================
__global__ void __launch_bounds__(256)
norm_k2(float* __restrict__ pattn)
{
    const int warp = threadIdx.x >> 5;
    const int lane = threadIdx.x & 31;
    const size_t row = (size_t)blockIdx.x * 8 + warp;   // < B*H*S = 131072
    const __half* er = e_scratch + row * SQ;
    float*        pr = pattn + row * SQ;

    uint2 d[16];
    float sum = 0.f;
    #pragma unroll
    for (int c = 0; c < 16; c++) {
        d[c] = *(const uint2*)(er + c * 128 + lane * 4);
        __half2 a = *(__half2*)&d[c].x, b = *(__half2*)&d[c].y;
        float2 fa = __half22float2(a), fb = __half22float2(b);
        sum += (fa.x + fa.y) + (fb.x + fb.y);
    }
    #pragma unroll
    for (int o = 16; o >= 1; o >>= 1) sum += __shfl_xor_sync(0xffffffffu, sum, o);
    float ri = (sum > 0.f) ? (1.f / sum) : 0.f;

    #pragma unroll
    for (int c = 0; c < 16; c++) {
        __half2 a = *(__half2*)&d[c].x, b = *(__half2*)&d[c].y;
        float2 fa = __half22float2(a), fb = __half22float2(b);
        float4 o4 = make_float4(fa.x * ri, fa.y * ri, fb.x * ri, fb.y * ri);
        *(float4*)(pr + c * 128 + lane * 4) = o4;
    }
}

extern "C" void kernel_launch(void* const* d_in, const int* in_sizes, int n_in,
                              void* d_out, int out_size)
{
    const float* q    = (const float*)d_in[0];
    const float* k    = (const float*)d_in[1];
    const float* v    = (const float*)d_in[2];
    const int*   mask = (const int*)d_in[3];

    float* outp  = (float*)d_out;                                   // [B,H,S,D]
    float* pattn = (float*)d_out + (size_t)B_ * H_ * SQ * DH;       // [B,H,S,S]

    cudaFuncSetAttribute(attn_k1, cudaFuncAttributeMaxDynamicSharedMemorySize, SMEM_BYTES);

    dim3 grid1(SQ / BM, B_ * H_);
    attn_k1<<<grid1, THREADS, SMEM_BYTES>>>(q, k, v, mask, outp);

    norm_k2<<<(B_ * H_ * SQ) / 8, 256>>>(pattn);
}

// round 8
// speedup vs baseline: 2.0065x; 1.0234x over previous
#include <cuda_runtime.h>
#include <cuda_fp16.h>
#include <cstdint>

#define B_  4
#define H_  16
#define SQ  2048
#define DH  64
#define BM  128
#define BN  64
#define NITER (SQ / BN)     // 32
#define THREADS 256
#define STRD 72             // fp16 smem row stride (halves)

// 512 MB device scratch: unnormalized exp(s) in fp16, layout [B*H*S, S]
__device__ __half e_scratch[(size_t)B_ * H_ * SQ * SQ];

// smem (halves): Qh[128*72] Ql[128*72] Kh[2][64*72] Kl[2][64*72] Vh[2][64*72]
#define SMEM_BYTES ((2*128*STRD + 6*64*STRD) * 2)   // 92160

__device__ __forceinline__ uint32_t smaddr(const void* p) {
    return (uint32_t)__cvta_generic_to_shared(p);
}
__device__ __forceinline__ void ldmx4(uint32_t r[4], uint32_t addr) {
    asm volatile("ldmatrix.sync.aligned.m8n8.x4.shared.b16 {%0,%1,%2,%3},[%4];"
                 : "=r"(r[0]), "=r"(r[1]), "=r"(r[2]), "=r"(r[3]) : "r"(addr));
}
__device__ __forceinline__ void ldmx4t(uint32_t r[4], uint32_t addr) {
    asm volatile("ldmatrix.sync.aligned.m8n8.x4.trans.shared.b16 {%0,%1,%2,%3},[%4];"
                 : "=r"(r[0]), "=r"(r[1]), "=r"(r[2]), "=r"(r[3]) : "r"(addr));
}
__device__ __forceinline__ void mma16816(float c[4], uint32_t a0, uint32_t a1, uint32_t a2,
                                         uint32_t a3, uint32_t b0, uint32_t b1) {
    asm volatile("mma.sync.aligned.m16n8k16.row.col.f32.f16.f16.f32 "
                 "{%0,%1,%2,%3},{%4,%5,%6,%7},{%8,%9},{%0,%1,%2,%3};"
                 : "+f"(c[0]), "+f"(c[1]), "+f"(c[2]), "+f"(c[3])
                 : "r"(a0), "r"(a1), "r"(a2), "r"(a3), "r"(b0), "r"(b1));
}
__device__ __forceinline__ uint32_t packh2(float a, float b) {
    __half2 h = __floats2half2_rn(a, b);
    return *(uint32_t*)&h;
}

// convert one fp32 float4 slice to hi/lo fp16 and store (8B each)
__device__ __forceinline__ void conv_split_sts(__half* Hi, __half* Lo, int r, int c4, float4 x) {
    const float* xv = (const float*)&x;
    __half h[4]; float lo[4];
    #pragma unroll
    for (int j = 0; j < 4; j++) { h[j] = __float2half_rn(xv[j]); lo[j] = xv[j] - __half2float(h[j]); }
    uint2 uh, ul;
    uh.x = packh2(__half2float(h[0]), __half2float(h[1]));
    uh.y = packh2(__half2float(h[2]), __half2float(h[3]));
    ul.x = packh2(lo[0], lo[1]);
    ul.y = packh2(lo[2], lo[3]);
    *(uint2*)&Hi[r * STRD + c4] = uh;
    *(uint2*)&Lo[r * STRD + c4] = ul;
}

// ==================== k1: QK, exp, e-store (fp16), PV, O ====================
__global__ void __launch_bounds__(THREADS, 2)
attn_k1(const float* __restrict__ q, const float* __restrict__ k,
        const float* __restrict__ v, const int* __restrict__ mask,
        float* __restrict__ outp)
{
    extern __shared__ __half sm[];
    __half* Qh  = sm;
    __half* Ql  = Qh + 128 * STRD;
    __half* KhB = Ql + 128 * STRD;            // 2 x 64*STRD
    __half* KlB = KhB + 2 * 64 * STRD;
    __half* VhB = KlB + 2 * 64 * STRD;

    const int tid  = threadIdx.x;
    const int lane = tid & 31;
    const int warp = tid >> 5;
    const int g    = lane >> 2;
    const int tq   = lane & 3;
    const int wrow = warp * 16;
    const int m0   = blockIdx.x * BM;
    const int bh   = blockIdx.y;

    const float* qb = q + (size_t)bh * SQ * DH;
    const float* kb = k + (size_t)bh * SQ * DH;
    const float* vb = v + (size_t)bh * SQ * DH;
    __half*      eb = e_scratch + (size_t)bh * SQ * SQ;

    // per-thread slice coords for 64x64 tile loads (4 float4 each)
    int tr[4], tc[4];
    #pragma unroll
    for (int i = 0; i < 4; i++) {
        int s = tid + i * THREADS;
        tr[i] = s >> 4;
        tc[i] = (s & 15) * 4;
    }

    // ---- prologue: load Q + split; load K0,V0 + convert into buf 0 ----
    #pragma unroll
    for (int i = 0; i < 8; i++) {
        int s  = tid + i * THREADS;
        int r  = s >> 4;
        int c4 = (s & 15) * 4;
        float4 x = *(const float4*)(qb + (size_t)(m0 + r) * DH + c4);
        conv_split_sts(Qh, Ql, r, c4, x);
    }
    {
        float4 kreg[4], vreg[4];
        #pragma unroll
        for (int i = 0; i < 4; i++) kreg[i] = *(const float4*)(kb + (size_t)tr[i] * DH + tc[i]);
        #pragma unroll
        for (int i = 0; i < 4; i++) vreg[i] = *(const float4*)(vb + (size_t)tr[i] * DH + tc[i]);
        #pragma unroll
        for (int i = 0; i < 4; i++) conv_split_sts(KhB, KlB, tr[i], tc[i], kreg[i]);
        #pragma unroll
        for (int i = 0; i < 4; i++) {
            uint2 uvh;
            uvh.x = packh2(vreg[i].x, vreg[i].y);
            uvh.y = packh2(vreg[i].z, vreg[i].w);
            *(uint2*)&VhB[tr[i] * STRD + tc[i]] = uvh;
        }
    }

    float oacc[8][4];
    #pragma unroll
    for (int j = 0; j < 8; j++) { oacc[j][0]=0.f; oacc[j][1]=0.f; oacc[j][2]=0.f; oacc[j][3]=0.f; }
    float rs0 = 0.f, rs1 = 0.f;
    const int prow0 = m0 + wrow + g;

    for (int it = 0; it < NITER; it++) {
        const int n0  = it * BN;
        const int nn  = ((it + 1 < NITER) ? (it + 1) : 0) * BN;
        const int cur = it & 1;
        const int nxt = cur ^ 1;
        __half* Kh = KhB + cur * 64 * STRD;
        __half* Kl = KlB + cur * 64 * STRD;
        __half* Vh = VhB + cur * 64 * STRD;

        __syncthreads();   // single barrier: cur buffers written, nxt buffers free

        // ---- prefetch K(it+1) into registers (batched LDG, hidden under compute) ----
        float4 kreg[4];
        #pragma unroll
        for (int i = 0; i < 4; i++)
            kreg[i] = *(const float4*)(kb + (size_t)(nn + tr[i]) * DH + tc[i]);

        // ---- QK^T: S[16x64] per warp, fp16 hi/lo 3-mma split ----
        float sacc[8][4];
        #pragma unroll
        for (int j = 0; j < 8; j++) { sacc[j][0]=0.f; sacc[j][1]=0.f; sacc[j][2]=0.f; sacc[j][3]=0.f; }

        #pragma unroll
        for (int kc = 0; kc < 4; kc++) {
            uint32_t aq[4], al[4];
            {
                int row = wrow + (lane & 15);
                int col = kc * 16 + ((lane & 16) ? 8 : 0);
                ldmx4(aq, smaddr(&Qh[row * STRD + col]));
                ldmx4(al, smaddr(&Ql[row * STRD + col]));
            }
            #pragma unroll
            for (int jp = 0; jp < 4; jp++) {
                uint32_t bh4[4], bl4[4];
                int row = jp * 16 + (lane & 7) + ((lane & 16) ? 8 : 0);
                int col = kc * 16 + ((lane & 8) ? 8 : 0);
                ldmx4(bh4, smaddr(&Kh[row * STRD + col]));
                ldmx4(bl4, smaddr(&Kl[row * STRD + col]));
                mma16816(sacc[2*jp],   aq[0],aq[1],aq[2],aq[3], bh4[0], bh4[1]);
                mma16816(sacc[2*jp],   aq[0],aq[1],aq[2],aq[3], bl4[0], bl4[1]);
                mma16816(sacc[2*jp],   al[0],al[1],al[2],al[3], bh4[0], bh4[1]);
                mma16816(sacc[2*jp+1], aq[0],aq[1],aq[2],aq[3], bh4[2], bh4[3]);
                mma16816(sacc[2*jp+1], aq[0],aq[1],aq[2],aq[3], bl4[2], bl4[3]);
                mma16816(sacc[2*jp+1], al[0],al[1],al[2],al[3], bh4[2], bh4[3]);
            }
        }

        // ---- prefetch V(it+1) into registers ----
        float4 vreg[4];
        #pragma unroll
        for (int i = 0; i < 4; i++)
            vreg[i] = *(const float4*)(vb + (size_t)(nn + tr[i]) * DH + tc[i]);

        // ---- mask, exp, rowsum, e-store (fp16 scratch), pack P ----
        uint32_t pk[8][2];
        #pragma unroll
        for (int j = 0; j < 8; j++) {
            int col = n0 + j * 8 + 2 * tq;
            int2 mz0 = *(const int2*)(mask + (size_t)prow0 * SQ + col);
            int2 mz1 = *(const int2*)(mask + (size_t)(prow0 + 8) * SQ + col);
            float e0 = mz0.x ? __expf(0.125f * sacc[j][0]) : 0.f;
            float e1 = mz0.y ? __expf(0.125f * sacc[j][1]) : 0.f;
            float e2 = mz1.x ? __expf(0.125f * sacc[j][2]) : 0.f;
            float e3 = mz1.y ? __expf(0.125f * sacc[j][3]) : 0.f;
            rs0 += e0 + e1;
            rs1 += e2 + e3;
            uint32_t p01 = packh2(e0, e1);
            uint32_t p23 = packh2(e2, e3);
            *(uint32_t*)(eb + (size_t)prow0 * SQ + col)       = p01;
            *(uint32_t*)(eb + (size_t)(prow0 + 8) * SQ + col) = p23;
            pk[j][0] = p01;
            pk[j][1] = p23;
        }

        // ---- convert K(it+1) regs -> nxt buffers (kreg dies here) ----
        #pragma unroll
        for (int i = 0; i < 4; i++)
            conv_split_sts(KhB + nxt * 64 * STRD, KlB + nxt * 64 * STRD, tr[i], tc[i], kreg[i]);

        // ---- O += P @ V ----
        #pragma unroll
        for (int kcp = 0; kcp < 4; kcp++) {
            uint32_t a0 = pk[2*kcp][0], a1 = pk[2*kcp][1];
            uint32_t a2 = pk[2*kcp+1][0], a3 = pk[2*kcp+1][1];
            #pragma unroll
            for (int jdp = 0; jdp < 4; jdp++) {
                uint32_t bv[4];
                int row = kcp * 16 + (lane & 7) + ((lane & 8) ? 8 : 0);
                int col = jdp * 16 + ((lane & 16) ? 8 : 0);
                ldmx4t(bv, smaddr(&Vh[row * STRD + col]));
                mma16816(oacc[2*jdp],   a0,a1,a2,a3, bv[0], bv[1]);
                mma16816(oacc[2*jdp+1], a0,a1,a2,a3, bv[2], bv[3]);
            }
        }

        // ---- convert V(it+1) regs -> nxt buffer ----
        #pragma unroll
        for (int i = 0; i < 4; i++) {
            uint2 uvh;
            uvh.x = packh2(vreg[i].x, vreg[i].y);
            uvh.y = packh2(vreg[i].z, vreg[i].w);
            *(uint2*)&(VhB + nxt * 64 * STRD)[tr[i] * STRD + tc[i]] = uvh;
        }
    }

    // ---- rowsum reduce within quad; write normalized O ----
    rs0 += __shfl_xor_sync(0xffffffffu, rs0, 1);
    rs0 += __shfl_xor_sync(0xffffffffu, rs0, 2);
    rs1 += __shfl_xor_sync(0xffffffffu, rs1, 1);
    rs1 += __shfl_xor_sync(0xffffffffu, rs1, 2);
    float ri0 = (rs0 > 0.f) ? (1.f / rs0) : 0.f;
    float ri1 = (rs1 > 0.f) ? (1.f / rs1) : 0.f;

    #pragma unroll
    for (int jd = 0; jd < 8; jd++) {
        int col = jd * 8 + 2 * tq;
        float2 o0; o0.x = oacc[jd][0] * ri0; o0.y = oacc[jd][1] * ri0;
        float2 o1; o1.x = oacc[jd][2] * ri1; o1.y = oacc[jd][3] * ri1;
        *(float2*)(outp + ((size_t)bh * SQ + prow0) * DH + col)     = o0;
        *(float2*)(outp + ((size_t)bh * SQ + prow0 + 8) * DH + col) = o1;
    }
}

// ==================== k2: stream-normalize p (1 warp / row) ====================
__global__ void __launch_bounds__(256)
norm_k2(float* __restrict__ pattn)
{
    const int warp = threadIdx.x >> 5;
    const int lane = threadIdx.x & 31;
    const size_t row = (size_t)blockIdx.x * 8 + warp;   // < B*H*S = 131072
    const __half* er = e_scratch + row * SQ;
    float*        pr = pattn + row * SQ;

    uint2 d[16];
    float sum = 0.f;
    #pragma unroll
    for (int c = 0; c < 16; c++) {
        d[c] = *(const uint2*)(er + c * 128 + lane * 4);
        __half2 a = *(__half2*)&d[c].x, b = *(__half2*)&d[c].y;
        float2 fa = __half22float2(a), fb = __half22float2(b);
        sum += (fa.x + fa.y) + (fb.x + fb.y);
    }
    #pragma unroll
    for (int o = 16; o >= 1; o >>= 1) sum += __shfl_xor_sync(0xffffffffu, sum, o);
    float ri = (sum > 0.f) ? (1.f / sum) : 0.f;

    #pragma unroll
    for (int c = 0; c < 16; c++) {
        __half2 a = *(__half2*)&d[c].x, b = *(__half2*)&d[c].y;
        float2 fa = __half22float2(a), fb = __half22float2(b);
        float4 o4 = make_float4(fa.x * ri, fa.y * ri, fb.x * ri, fb.y * ri);
        *(float4*)(pr + c * 128 + lane * 4) = o4;
    }
}

extern "C" void kernel_launch(void* const* d_in, const int* in_sizes, int n_in,
                              void* d_out, int out_size)
{
    const float* q    = (const float*)d_in[0];
    const float* k    = (const float*)d_in[1];
    const float* v    = (const float*)d_in[2];
    const int*   mask = (const int*)d_in[3];

    float* outp  = (float*)d_out;                                   // [B,H,S,D]
    float* pattn = (float*)d_out + (size_t)B_ * H_ * SQ * DH;       // [B,H,S,S]

    cudaFuncSetAttribute(attn_k1, cudaFuncAttributeMaxDynamicSharedMemorySize, SMEM_BYTES);

    dim3 grid1(SQ / BM, B_ * H_);
    attn_k1<<<grid1, THREADS, SMEM_BYTES>>>(q, k, v, mask, outp);

    norm_k2<<<(B_ * H_ * SQ) / 8, 256>>>(pattn);
}

// round 14
// speedup vs baseline: 2.0892x; 1.0412x over previous
#include <cuda_runtime.h>
#include <cuda_fp16.h>
#include <cstdint>

#define B_  4
#define H_  16
#define SQ  2048
#define DH  64
#define BM  128
#define BN  64
#define NITER (SQ / BN)     // 32
#define THREADS 256
#define STRD 72             // fp16 smem row stride (halves)

// 512 MB device scratch: unnormalized exp(s) in fp16, layout [B*H*S, S]
__device__ __half e_scratch[(size_t)B_ * H_ * SQ * SQ];

// smem (halves): Qh[128*72] Ql[128*72] Kh[2][64*72] Vh[2][64*72]
#define SMEM_BYTES ((2*128*STRD + 4*64*STRD) * 2)   // 73728

__device__ __forceinline__ uint32_t smaddr(const void* p) {
    return (uint32_t)__cvta_generic_to_shared(p);
}
__device__ __forceinline__ void ldmx4(uint32_t r[4], uint32_t addr) {
    asm volatile("ldmatrix.sync.aligned.m8n8.x4.shared.b16 {%0,%1,%2,%3},[%4];"
                 : "=r"(r[0]), "=r"(r[1]), "=r"(r[2]), "=r"(r[3]) : "r"(addr));
}
__device__ __forceinline__ void ldmx4t(uint32_t r[4], uint32_t addr) {
    asm volatile("ldmatrix.sync.aligned.m8n8.x4.trans.shared.b16 {%0,%1,%2,%3},[%4];"
                 : "=r"(r[0]), "=r"(r[1]), "=r"(r[2]), "=r"(r[3]) : "r"(addr));
}
__device__ __forceinline__ void mma16816(float c[4], uint32_t a0, uint32_t a1, uint32_t a2,
                                         uint32_t a3, uint32_t b0, uint32_t b1) {
    asm volatile("mma.sync.aligned.m16n8k16.row.col.f32.f16.f16.f32 "
                 "{%0,%1,%2,%3},{%4,%5,%6,%7},{%8,%9},{%0,%1,%2,%3};"
                 : "+f"(c[0]), "+f"(c[1]), "+f"(c[2]), "+f"(c[3])
                 : "r"(a0), "r"(a1), "r"(a2), "r"(a3), "r"(b0), "r"(b1));
}
__device__ __forceinline__ uint32_t packh2(float a, float b) {
    __half2 h = __floats2half2_rn(a, b);
    return *(uint32_t*)&h;
}

// convert one fp32 float4 slice to hi/lo fp16 and store (8B each)
__device__ __forceinline__ void conv_split_sts(__half* Hi, __half* Lo, int r, int c4, float4 x) {
    const float* xv = (const float*)&x;
    __half h[4]; float lo[4];
    #pragma unroll
    for (int j = 0; j < 4; j++) { h[j] = __float2half_rn(xv[j]); lo[j] = xv[j] - __half2float(h[j]); }
    uint2 uh, ul;
    uh.x = packh2(__half2float(h[0]), __half2float(h[1]));
    uh.y = packh2(__half2float(h[2]), __half2float(h[3]));
    ul.x = packh2(lo[0], lo[1]);
    ul.y = packh2(lo[2], lo[3]);
    *(uint2*)&Hi[r * STRD + c4] = uh;
    *(uint2*)&Lo[r * STRD + c4] = ul;
}

// convert fp32 float4 -> fp16 (hi only), 8B store
__device__ __forceinline__ void conv_hi_sts(__half* Hi, int r, int c4, float4 x) {
    uint2 uh;
    uh.x = packh2(x.x, x.y);
    uh.y = packh2(x.z, x.w);
    *(uint2*)&Hi[r * STRD + c4] = uh;
}

// ==================== k1: QK, exp, e-store (fp16), PV, O ====================
__global__ void __launch_bounds__(THREADS, 2)
attn_k1(const float* __restrict__ q, const float* __restrict__ k,
        const float* __restrict__ v, const int* __restrict__ mask,
        float* __restrict__ outp)
{
    extern __shared__ __half sm[];
    __half* Qh  = sm;
    __half* Ql  = Qh + 128 * STRD;
    __half* KhB = Ql + 128 * STRD;            // 2 x 64*STRD
    __half* VhB = KhB + 2 * 64 * STRD;        // 2 x 64*STRD

    const int tid  = threadIdx.x;
    const int lane = tid & 31;
    const int warp = tid >> 5;
    const int g    = lane >> 2;
    const int tq   = lane & 3;
    const int wrow = warp * 16;
    const int m0   = blockIdx.x * BM;
    const int bh   = blockIdx.y;

    const float* qb = q + (size_t)bh * SQ * DH;
    const float* kb = k + (size_t)bh * SQ * DH;
    const float* vb = v + (size_t)bh * SQ * DH;
    __half*      eb = e_scratch + (size_t)bh * SQ * SQ;

    // per-thread slice coords for 64x64 tile loads (4 float4 each)
    int tr[4], tc[4];
    #pragma unroll
    for (int i = 0; i < 4; i++) {
        int s = tid + i * THREADS;
        tr[i] = s >> 4;
        tc[i] = (s & 15) * 4;
    }

    // ---- prologue: load Q + split; load K0,V0 + convert into buf 0 ----
    #pragma unroll
    for (int i = 0; i < 8; i++) {
        int s  = tid + i * THREADS;
        int r  = s >> 4;
        int c4 = (s & 15) * 4;
        float4 x = *(const float4*)(qb + (size_t)(m0 + r) * DH + c4);
        conv_split_sts(Qh, Ql, r, c4, x);
    }
    {
        float4 kreg[4], vreg[4];
        #pragma unroll
        for (int i = 0; i < 4; i++) kreg[i] = *(const float4*)(kb + (size_t)tr[i] * DH + tc[i]);
        #pragma unroll
        for (int i = 0; i < 4; i++) vreg[i] = *(const float4*)(vb + (size_t)tr[i] * DH + tc[i]);
        #pragma unroll
        for (int i = 0; i < 4; i++) conv_hi_sts(KhB, tr[i], tc[i], kreg[i]);
        #pragma unroll
        for (int i = 0; i < 4; i++) conv_hi_sts(VhB, tr[i], tc[i], vreg[i]);
    }

    float oacc[8][4];
    #pragma unroll
    for (int j = 0; j < 8; j++) { oacc[j][0]=0.f; oacc[j][1]=0.f; oacc[j][2]=0.f; oacc[j][3]=0.f; }
    float rs0 = 0.f, rs1 = 0.f;
    const int prow0 = m0 + wrow + g;

    for (int it = 0; it < NITER; it++) {
        const int n0  = it * BN;
        const int nn  = ((it + 1 < NITER) ? (it + 1) : 0) * BN;
        const int cur = it & 1;
        const int nxt = cur ^ 1;
        __half* Kh = KhB + cur * 64 * STRD;
        __half* Vh = VhB + cur * 64 * STRD;

        __syncthreads();   // single barrier: cur buffers written, nxt buffers free

        // ---- prefetch K(it+1) into registers (hidden under compute) ----
        float4 kreg[4];
        #pragma unroll
        for (int i = 0; i < 4; i++)
            kreg[i] = *(const float4*)(kb + (size_t)(nn + tr[i]) * DH + tc[i]);

        // ---- QK^T: S[16x64] per warp; S = (Qh+Ql)·Kh, 2-mma split ----
        float sacc[8][4];
        #pragma unroll
        for (int j = 0; j < 8; j++) { sacc[j][0]=0.f; sacc[j][1]=0.f; sacc[j][2]=0.f; sacc[j][3]=0.f; }

        #pragma unroll
        for (int kc = 0; kc < 4; kc++) {
            uint32_t aq[4], al[4];
            {
                int row = wrow + (lane & 15);
                int col = kc * 16 + ((lane & 16) ? 8 : 0);
                ldmx4(aq, smaddr(&Qh[row * STRD + col]));
                ldmx4(al, smaddr(&Ql[row * STRD + col]));
            }
            #pragma unroll
            for (int jp = 0; jp < 4; jp++) {
                uint32_t bh4[4];
                int row = jp * 16 + (lane & 7) + ((lane & 16) ? 8 : 0);
                int col = kc * 16 + ((lane & 8) ? 8 : 0);
                ldmx4(bh4, smaddr(&Kh[row * STRD + col]));
                mma16816(sacc[2*jp],   aq[0],aq[1],aq[2],aq[3], bh4[0], bh4[1]);
                mma16816(sacc[2*jp],   al[0],al[1],al[2],al[3], bh4[0], bh4[1]);
                mma16816(sacc[2*jp+1], aq[0],aq[1],aq[2],aq[3], bh4[2], bh4[3]);
                mma16816(sacc[2*jp+1], al[0],al[1],al[2],al[3], bh4[2], bh4[3]);
            }
        }

        // ---- prefetch V(it+1) into registers ----
        float4 vreg[4];
        #pragma unroll
        for (int i = 0; i < 4; i++)
            vreg[i] = *(const float4*)(vb + (size_t)(nn + tr[i]) * DH + tc[i]);

        // ---- mask, exp, rowsum, e-store (fp16 scratch), pack P ----
        uint32_t pk[8][2];
        #pragma unroll
        for (int j = 0; j < 8; j++) {
            int col = n0 + j * 8 + 2 * tq;
            int2 mz0 = *(const int2*)(mask + (size_t)prow0 * SQ + col);
            int2 mz1 = *(const int2*)(mask + (size_t)(prow0 + 8) * SQ + col);
            float e0 = mz0.x ? __expf(0.125f * sacc[j][0]) : 0.f;
            float e1 = mz0.y ? __expf(0.125f * sacc[j][1]) : 0.f;
            float e2 = mz1.x ? __expf(0.125f * sacc[j][2]) : 0.f;
            float e3 = mz1.y ? __expf(0.125f * sacc[j][3]) : 0.f;
            rs0 += e0 + e1;
            rs1 += e2 + e3;
            uint32_t p01 = packh2(e0, e1);
            uint32_t p23 = packh2(e2, e3);
            *(uint32_t*)(eb + (size_t)prow0 * SQ + col)       = p01;
            *(uint32_t*)(eb + (size_t)(prow0 + 8) * SQ + col) = p23;
            pk[j][0] = p01;
            pk[j][1] = p23;
        }

        // ---- convert K(it+1) regs -> nxt buffer (kreg dies here) ----
        #pragma unroll
        for (int i = 0; i < 4; i++)
            conv_hi_sts(KhB + nxt * 64 * STRD, tr[i], tc[i], kreg[i]);

        // ---- O += P @ V ----
        #pragma unroll
        for (int kcp = 0; kcp < 4; kcp++) {
            uint32_t a0 = pk[2*kcp][0], a1 = pk[2*kcp][1];
            uint32_t a2 = pk[2*kcp+1][0], a3 = pk[2*kcp+1][1];
            #pragma unroll
            for (int jdp = 0; jdp < 4; jdp++) {
                uint32_t bv[4];
                int row = kcp * 16 + (lane & 7) + ((lane & 8) ? 8 : 0);
                int col = jdp * 16 + ((lane & 16) ? 8 : 0);
                ldmx4t(bv, smaddr(&Vh[row * STRD + col]));
                mma16816(oacc[2*jdp],   a0,a1,a2,a3, bv[0], bv[1]);
                mma16816(oacc[2*jdp+1], a0,a1,a2,a3, bv[2], bv[3]);
            }
        }

        // ---- convert V(it+1) regs -> nxt buffer ----
        #pragma unroll
        for (int i = 0; i < 4; i++)
            conv_hi_sts(VhB + nxt * 64 * STRD, tr[i], tc[i], vreg[i]);
    }

    // ---- rowsum reduce within quad; write normalized O ----
    rs0 += __shfl_xor_sync(0xffffffffu, rs0, 1);
    rs0 += __shfl_xor_sync(0xffffffffu, rs0, 2);
    rs1 += __shfl_xor_sync(0xffffffffu, rs1, 1);
    rs1 += __shfl_xor_sync(0xffffffffu, rs1, 2);
    float ri0 = (rs0 > 0.f) ? (1.f / rs0) : 0.f;
    float ri1 = (rs1 > 0.f) ? (1.f / rs1) : 0.f;

    #pragma unroll
    for (int jd = 0; jd < 8; jd++) {
        int col = jd * 8 + 2 * tq;
        float2 o0; o0.x = oacc[jd][0] * ri0; o0.y = oacc[jd][1] * ri0;
        float2 o1; o1.x = oacc[jd][2] * ri1; o1.y = oacc[jd][3] * ri1;
        *(float2*)(outp + ((size_t)bh * SQ + prow0) * DH + col)     = o0;
        *(float2*)(outp + ((size_t)bh * SQ + prow0 + 8) * DH + col) = o1;
    }
}

// ==================== k2: stream-normalize p (1 warp / row) ====================
__global__ void __launch_bounds__(256)
norm_k2(float* __restrict__ pattn)
{
    const int warp = threadIdx.x >> 5;
    const int lane = threadIdx.x & 31;
    const size_t row = (size_t)blockIdx.x * 8 + warp;   // < B*H*S = 131072
    const __half* er = e_scratch + row * SQ;
    float*        pr = pattn + row * SQ;

    uint2 d[16];
    float sum = 0.f;
    #pragma unroll
    for (int c = 0; c < 16; c++) {
        d[c] = *(const uint2*)(er + c * 128 + lane * 4);
        __half2 a = *(__half2*)&d[c].x, b = *(__half2*)&d[c].y;
        float2 fa = __half22float2(a), fb = __half22float2(b);
        sum += (fa.x + fa.y) + (fb.x + fb.y);
    }
    #pragma unroll
    for (int o = 16; o >= 1; o >>= 1) sum += __shfl_xor_sync(0xffffffffu, sum, o);
    float ri = (sum > 0.f) ? (1.f / sum) : 0.f;

    #pragma unroll
    for (int c = 0; c < 16; c++) {
        __half2 a = *(__half2*)&d[c].x, b = *(__half2*)&d[c].y;
        float2 fa = __half22float2(a), fb = __half22float2(b);
        float4 o4 = make_float4(fa.x * ri, fa.y * ri, fb.x * ri, fb.y * ri);
        *(float4*)(pr + c * 128 + lane * 4) = o4;
    }
}

extern "C" void kernel_launch(void* const* d_in, const int* in_sizes, int n_in,
                              void* d_out, int out_size)
{
    const float* q    = (const float*)d_in[0];
    const float* k    = (const float*)d_in[1];
    const float* v    = (const float*)d_in[2];
    const int*   mask = (const int*)d_in[3];

    float* outp  = (float*)d_out;                                   // [B,H,S,D]
    float* pattn = (float*)d_out + (size_t)B_ * H_ * SQ * DH;       // [B,H,S,S]

    cudaFuncSetAttribute(attn_k1, cudaFuncAttributeMaxDynamicSharedMemorySize, SMEM_BYTES);

    dim3 grid1(SQ / BM, B_ * H_);
    attn_k1<<<grid1, THREADS, SMEM_BYTES>>>(q, k, v, mask, outp);

    norm_k2<<<(B_ * H_ * SQ) / 8, 256>>>(pattn);
}

// round 15
// speedup vs baseline: 2.4766x; 1.1855x over previous
#include <cuda_runtime.h>
#include <cuda_fp16.h>
#include <cstdint>

#define B_  4
#define H_  16
#define SQ  2048
#define DH  64
#define BM  128
#define BN  64
#define NITER (SQ / BN)     // 32
#define THREADS 256
#define STRD 72             // fp16 smem row stride (halves)
#define QSCALE 0.1803368801111137f   // 0.125 * log2(e)

// 512 MB device scratch: unnormalized exp(s) in fp16, layout [B*H*S, S]
__device__ __half e_scratch[(size_t)B_ * H_ * SQ * SQ];
// packed mask bits: [S][32] uint64, bit c of word w = mask[row][w*64+c]
__device__ uint64_t mbits_g[(size_t)SQ * 32];

// smem (halves): Qh[128*72] Kh[2][64*72] Vh[2][64*72]
#define SMEM_BYTES ((128*STRD + 4*64*STRD) * 2)   // 55296

__device__ __forceinline__ uint32_t smaddr(const void* p) {
    return (uint32_t)__cvta_generic_to_shared(p);
}
__device__ __forceinline__ float ex2f(float x) {
    float r;
    asm("ex2.approx.f32 %0,%1;" : "=f"(r) : "f"(x));
    return r;
}
__device__ __forceinline__ void ldmx4(uint32_t r[4], uint32_t addr) {
    asm volatile("ldmatrix.sync.aligned.m8n8.x4.shared.b16 {%0,%1,%2,%3},[%4];"
                 : "=r"(r[0]), "=r"(r[1]), "=r"(r[2]), "=r"(r[3]) : "r"(addr));
}
__device__ __forceinline__ void ldmx4t(uint32_t r[4], uint32_t addr) {
    asm volatile("ldmatrix.sync.aligned.m8n8.x4.trans.shared.b16 {%0,%1,%2,%3},[%4];"
                 : "=r"(r[0]), "=r"(r[1]), "=r"(r[2]), "=r"(r[3]) : "r"(addr));
}
__device__ __forceinline__ void mma16816(float c[4], uint32_t a0, uint32_t a1, uint32_t a2,
                                         uint32_t a3, uint32_t b0, uint32_t b1) {
    asm volatile("mma.sync.aligned.m16n8k16.row.col.f32.f16.f16.f32 "
                 "{%0,%1,%2,%3},{%4,%5,%6,%7},{%8,%9},{%0,%1,%2,%3};"
                 : "+f"(c[0]), "+f"(c[1]), "+f"(c[2]), "+f"(c[3])
                 : "r"(a0), "r"(a1), "r"(a2), "r"(a3), "r"(b0), "r"(b1));
}
__device__ __forceinline__ uint32_t packh2(float a, float b) {
    __half2 h = __floats2half2_rn(a, b);
    return *(uint32_t*)&h;
}
// convert fp32 float4 -> fp16 (optionally pre-scaled), 8B store
__device__ __forceinline__ void conv_hi_sts(__half* Hi, int r, int c4, float4 x) {
    uint2 uh;
    uh.x = packh2(x.x, x.y);
    uh.y = packh2(x.z, x.w);
    *(uint2*)&Hi[r * STRD + c4] = uh;
}

// ==================== k0: pack mask into bits ====================
__global__ void __launch_bounds__(256)
pack_mask(const int* __restrict__ mask)
{
    const int warp = (blockIdx.x * 256 + threadIdx.x) >> 5;   // row 0..2047
    const int lane = threadIdx.x & 31;
    if (warp >= SQ) return;
    const int* mr = mask + (size_t)warp * SQ;
    #pragma unroll 4
    for (int w = 0; w < 32; w++) {
        int m0 = mr[w * 64 + lane];
        int m1 = mr[w * 64 + 32 + lane];
        uint32_t b0 = __ballot_sync(0xffffffffu, m0 != 0);
        uint32_t b1 = __ballot_sync(0xffffffffu, m1 != 0);
        if (lane == 0) mbits_g[(size_t)warp * 32 + w] = (uint64_t)b0 | ((uint64_t)b1 << 32);
    }
}

// ==================== k1: QK, exp, e-store (fp16), PV, O ====================
__global__ void __launch_bounds__(THREADS, 2)
attn_k1(const float* __restrict__ q, const float* __restrict__ k,
        const float* __restrict__ v, float* __restrict__ outp)
{
    extern __shared__ __half sm[];
    __half* Qh  = sm;
    __half* KhB = Qh + 128 * STRD;            // 2 x 64*STRD
    __half* VhB = KhB + 2 * 64 * STRD;        // 2 x 64*STRD

    const int tid  = threadIdx.x;
    const int lane = tid & 31;
    const int warp = tid >> 5;
    const int g    = lane >> 2;
    const int tq   = lane & 3;
    const int wrow = warp * 16;
    const int m0   = blockIdx.x * BM;
    const int bh   = blockIdx.y;

    const float* qb = q + (size_t)bh * SQ * DH;
    const float* kb = k + (size_t)bh * SQ * DH;
    const float* vb = v + (size_t)bh * SQ * DH;
    __half*      eb = e_scratch + (size_t)bh * SQ * SQ;

    // per-thread slice coords for 64x64 tile loads (4 float4 each)
    int tr[4], tc[4];
    #pragma unroll
    for (int i = 0; i < 4; i++) {
        int s = tid + i * THREADS;
        tr[i] = s >> 4;
        tc[i] = (s & 15) * 4;
    }

    // ---- prologue: load Q (pre-scaled by 0.125*log2e) ; K0,V0 -> buf 0 ----
    #pragma unroll
    for (int i = 0; i < 8; i++) {
        int s  = tid + i * THREADS;
        int r  = s >> 4;
        int c4 = (s & 15) * 4;
        float4 x = *(const float4*)(qb + (size_t)(m0 + r) * DH + c4);
        x.x *= QSCALE; x.y *= QSCALE; x.z *= QSCALE; x.w *= QSCALE;
        conv_hi_sts(Qh, r, c4, x);
    }
    {
        float4 kreg[4], vreg[4];
        #pragma unroll
        for (int i = 0; i < 4; i++) kreg[i] = *(const float4*)(kb + (size_t)tr[i] * DH + tc[i]);
        #pragma unroll
        for (int i = 0; i < 4; i++) vreg[i] = *(const float4*)(vb + (size_t)tr[i] * DH + tc[i]);
        #pragma unroll
        for (int i = 0; i < 4; i++) conv_hi_sts(KhB, tr[i], tc[i], kreg[i]);
        #pragma unroll
        for (int i = 0; i < 4; i++) conv_hi_sts(VhB, tr[i], tc[i], vreg[i]);
    }

    float oacc[8][4];
    #pragma unroll
    for (int j = 0; j < 8; j++) { oacc[j][0]=0.f; oacc[j][1]=0.f; oacc[j][2]=0.f; oacc[j][3]=0.f; }
    float rs0 = 0.f, rs1 = 0.f;
    const int prow0 = m0 + wrow + g;
    const int shb = 2 * tq;    // base bit shift within each 8-bit group

    for (int it = 0; it < NITER; it++) {
        const int n0  = it * BN;
        const int nn  = ((it + 1 < NITER) ? (it + 1) : 0) * BN;
        const int cur = it & 1;
        const int nxt = cur ^ 1;
        __half* Kh = KhB + cur * 64 * STRD;
        __half* Vh = VhB + cur * 64 * STRD;

        __syncthreads();   // single barrier: cur buffers written, nxt buffers free

        // ---- prefetch K(it+1) into registers (hidden under compute) ----
        float4 kreg[4];
        #pragma unroll
        for (int i = 0; i < 4; i++)
            kreg[i] = *(const float4*)(kb + (size_t)(nn + tr[i]) * DH + tc[i]);

        // ---- packed mask words for this thread's two rows ----
        uint64_t w0 = mbits_g[(size_t)prow0 * 32 + it];
        uint64_t w1 = mbits_g[(size_t)(prow0 + 8) * 32 + it];

        // ---- QK^T: S[16x64] per warp; single fp16 MMA (Q pre-scaled) ----
        float sacc[8][4];
        #pragma unroll
        for (int j = 0; j < 8; j++) { sacc[j][0]=0.f; sacc[j][1]=0.f; sacc[j][2]=0.f; sacc[j][3]=0.f; }

        #pragma unroll
        for (int kc = 0; kc < 4; kc++) {
            uint32_t aq[4];
            {
                int row = wrow + (lane & 15);
                int col = kc * 16 + ((lane & 16) ? 8 : 0);
                ldmx4(aq, smaddr(&Qh[row * STRD + col]));
            }
            #pragma unroll
            for (int jp = 0; jp < 4; jp++) {
                uint32_t bh4[4];
                int row = jp * 16 + (lane & 7) + ((lane & 16) ? 8 : 0);
                int col = kc * 16 + ((lane & 8) ? 8 : 0);
                ldmx4(bh4, smaddr(&Kh[row * STRD + col]));
                mma16816(sacc[2*jp],   aq[0],aq[1],aq[2],aq[3], bh4[0], bh4[1]);
                mma16816(sacc[2*jp+1], aq[0],aq[1],aq[2],aq[3], bh4[2], bh4[3]);
            }
        }

        // ---- prefetch V(it+1) into registers ----
        float4 vreg[4];
        #pragma unroll
        for (int i = 0; i < 4; i++)
            vreg[i] = *(const float4*)(vb + (size_t)(nn + tr[i]) * DH + tc[i]);

        // ---- mask bits, exp2, rowsum, e-store (fp16 scratch), pack P ----
        uint32_t pk[8][2];
        #pragma unroll
        for (int j = 0; j < 8; j++) {
            int col = n0 + j * 8 + shb;
            uint32_t b0 = (uint32_t)(w0 >> (8 * j + shb));
            uint32_t b1 = (uint32_t)(w1 >> (8 * j + shb));
            float e0 = (b0 & 1u) ? ex2f(sacc[j][0]) : 0.f;
            float e1 = (b0 & 2u) ? ex2f(sacc[j][1]) : 0.f;
            float e2 = (b1 & 1u) ? ex2f(sacc[j][2]) : 0.f;
            float e3 = (b1 & 2u) ? ex2f(sacc[j][3]) : 0.f;
            rs0 += e0 + e1;
            rs1 += e2 + e3;
            uint32_t p01 = packh2(e0, e1);
            uint32_t p23 = packh2(e2, e3);
            *(uint32_t*)(eb + (size_t)prow0 * SQ + col)       = p01;
            *(uint32_t*)(eb + (size_t)(prow0 + 8) * SQ + col) = p23;
            pk[j][0] = p01;
            pk[j][1] = p23;
        }

        // ---- convert K(it+1) regs -> nxt buffer (kreg dies here) ----
        #pragma unroll
        for (int i = 0; i < 4; i++)
            conv_hi_sts(KhB + nxt * 64 * STRD, tr[i], tc[i], kreg[i]);

        // ---- O += P @ V ----
        #pragma unroll
        for (int kcp = 0; kcp < 4; kcp++) {
            uint32_t a0 = pk[2*kcp][0], a1 = pk[2*kcp][1];
            uint32_t a2 = pk[2*kcp+1][0], a3 = pk[2*kcp+1][1];
            #pragma unroll
            for (int jdp = 0; jdp < 4; jdp++) {
                uint32_t bv[4];
                int row = kcp * 16 + (lane & 7) + ((lane & 8) ? 8 : 0);
                int col = jdp * 16 + ((lane & 16) ? 8 : 0);
                ldmx4t(bv, smaddr(&Vh[row * STRD + col]));
                mma16816(oacc[2*jdp],   a0,a1,a2,a3, bv[0], bv[1]);
                mma16816(oacc[2*jdp+1], a0,a1,a2,a3, bv[2], bv[3]);
            }
        }

        // ---- convert V(it+1) regs -> nxt buffer ----
        #pragma unroll
        for (int i = 0; i < 4; i++)
            conv_hi_sts(VhB + nxt * 64 * STRD, tr[i], tc[i], vreg[i]);
    }

    // ---- rowsum reduce within quad; write normalized O ----
    rs0 += __shfl_xor_sync(0xffffffffu, rs0, 1);
    rs0 += __shfl_xor_sync(0xffffffffu, rs0, 2);
    rs1 += __shfl_xor_sync(0xffffffffu, rs1, 1);
    rs1 += __shfl_xor_sync(0xffffffffu, rs1, 2);
    float ri0 = (rs0 > 0.f) ? (1.f / rs0) : 0.f;
    float ri1 = (rs1 > 0.f) ? (1.f / rs1) : 0.f;

    #pragma unroll
    for (int jd = 0; jd < 8; jd++) {
        int col = jd * 8 + 2 * tq;
        float2 o0; o0.x = oacc[jd][0] * ri0; o0.y = oacc[jd][1] * ri0;
        float2 o1; o1.x = oacc[jd][2] * ri1; o1.y = oacc[jd][3] * ri1;
        *(float2*)(outp + ((size_t)bh * SQ + prow0) * DH + col)     = o0;
        *(float2*)(outp + ((size_t)bh * SQ + prow0 + 8) * DH + col) = o1;
    }
}

// ==================== k2: stream-normalize p (1 warp / row) ====================
__global__ void __launch_bounds__(256)
norm_k2(float* __restrict__ pattn)
{
    const int warp = threadIdx.x >> 5;
    const int lane = threadIdx.x & 31;
    const size_t row = (size_t)blockIdx.x * 8 + warp;   // < B*H*S = 131072
    const __half* er = e_scratch + row * SQ;
    float*        pr = pattn + row * SQ;

    uint2 d[16];
    float sum = 0.f;
    #pragma unroll
    for (int c = 0; c < 16; c++) {
        d[c] = *(const uint2*)(er + c * 128 + lane * 4);
        __half2 a = *(__half2*)&d[c].x, b = *(__half2*)&d[c].y;
        float2 fa = __half22float2(a), fb = __half22float2(b);
        sum += (fa.x + fa.y) + (fb.x + fb.y);
    }
    #pragma unroll
    for (int o = 16; o >= 1; o >>= 1) sum += __shfl_xor_sync(0xffffffffu, sum, o);
    float ri = (sum > 0.f) ? (1.f / sum) : 0.f;

    #pragma unroll
    for (int c = 0; c < 16; c++) {
        __half2 a = *(__half2*)&d[c].x, b = *(__half2*)&d[c].y;
        float2 fa = __half22float2(a), fb = __half22float2(b);
        float4 o4 = make_float4(fa.x * ri, fa.y * ri, fb.x * ri, fb.y * ri);
        *(float4*)(pr + c * 128 + lane * 4) = o4;
    }
}

extern "C" void kernel_launch(void* const* d_in, const int* in_sizes, int n_in,
                              void* d_out, int out_size)
{
    const float* q    = (const float*)d_in[0];
    const float* k    = (const float*)d_in[1];
    const float* v    = (const float*)d_in[2];
    const int*   mask = (const int*)d_in[3];

    float* outp  = (float*)d_out;                                   // [B,H,S,D]
    float* pattn = (float*)d_out + (size_t)B_ * H_ * SQ * DH;       // [B,H,S,S]

    cudaFuncSetAttribute(attn_k1, cudaFuncAttributeMaxDynamicSharedMemorySize, SMEM_BYTES);

    pack_mask<<<SQ * 32 / 256, 256>>>(mask);

    dim3 grid1(SQ / BM, B_ * H_);
    attn_k1<<<grid1, THREADS, SMEM_BYTES>>>(q, k, v, outp);

    norm_k2<<<(B_ * H_ * SQ) / 8, 256>>>(pattn);
}